// round 17
// baseline (speedup 1.0000x reference)
#include <cuda_runtime.h>

#define NN 50000
#define EE 800000
#define GG 64
#define HH 64
#define LL 3
#define CC 4
#define NH (NN*HH)
#define NB 296                 // 2 blocks/SM x 148 SMs, all co-resident
#define NT 256
#define NODE_CHUNK 169         // ceil(50000/296)

typedef unsigned long long ull;

// ---------------------------------------------------------------------------
// Scratch
// ---------------------------------------------------------------------------
__device__ __align__(16) float g_x[NH];
__device__ __align__(16) float g_h[NH];
__device__ int   g_rowptr[NN+1];
__device__ int   g_cursor[NN];
__device__ int   g_deg[NN];
__device__ int   g_csrc[EE];
__device__ float g_stats[LL*CC*128];
__device__ float g_z[GG*HH*LL];
__device__ float g_h1[GG*HH];
__device__ float g_bnp[128];
__device__ int   g_ccnt[CC];
__device__ int   g_coff[CC+1];
__device__ int   g_ccur[CC];
__device__ int   g_clist[NN];
__device__ int   g_bsum[NB];
__device__ int   g_boff[NB];
__device__ int   g_is64;
__device__ unsigned int g_bar_arrive;
__device__ unsigned int g_bar_gen;

__device__ __forceinline__ int load_idx(const void* p, long long i, int is64) {
    if (is64) return (int)((const long long*)p)[i];
    return ((const int*)p)[i];
}

// Software grid barrier (all NB blocks co-resident by construction)
__device__ __forceinline__ void grid_barrier() {
    __syncthreads();
    if (threadIdx.x == 0) {
        __threadfence();
        volatile unsigned int* genp = &g_bar_gen;
        unsigned int gen = *genp;
        if (atomicAdd(&g_bar_arrive, 1u) == NB - 1) {
            g_bar_arrive = 0;
            __threadfence();
            *genp = gen + 1;
        } else {
            while (*genp == gen) { }
        }
    }
    __syncthreads();
}

// packed f32x2 helpers
__device__ __forceinline__ void fma2(ull& d, ull a, ull b) {
    asm("fma.rn.f32x2 %0, %1, %2, %0;" : "+l"(d) : "l"(a), "l"(b));
}
__device__ __forceinline__ ull add2(ull a, ull b) {
    ull r; asm("add.rn.f32x2 %0, %1, %2;" : "=l"(r) : "l"(a), "l"(b)); return r;
}
__device__ __forceinline__ ull pack2(float lo, float hi) {
    ull r; asm("mov.b64 %0, {%1,%2};" : "=l"(r) : "f"(lo), "f"(hi)); return r;
}
__device__ __forceinline__ void unpack2(ull v, float& lo, float& hi) {
    asm("mov.b64 {%0,%1}, %2;" : "=f"(lo), "=f"(hi) : "l"(v));
}
__device__ __forceinline__ ull ldgx2(int node, int l2) {
    return *(const ull*)(g_x + (size_t)node * 64 + l2);
}

// ---------------------------------------------------------------------------
// Single persistent kernel: everything
// ---------------------------------------------------------------------------
__global__ void __launch_bounds__(NT, 2) persistent_kernel(
        const float* __restrict__ x, const int* __restrict__ cl,
        const void* __restrict__ eidx, const void* __restrict__ batch,
        const float* __restrict__ W1, const float* __restrict__ b1,
        const float* __restrict__ g1, const float* __restrict__ be1,
        const float* __restrict__ W2, const float* __restrict__ b2,
        const float* __restrict__ Wp1, const float* __restrict__ bp1,
        const float* __restrict__ gp,  const float* __restrict__ bep,
        const float* __restrict__ Wp2, const float* __restrict__ bp2,
        float* __restrict__ out) {
    __shared__ __align__(16) float Wsh1[4096];
    __shared__ __align__(16) float Wsh2[4096];
    __shared__ __align__(16) float hdup[8][128];    // per-warp lane-duplicated h
    __shared__ __align__(16) int   esh[8][2][64];   // per-warp staged edge lists
    __shared__ float s1sh[64], s2sh[64];

    const int tid = threadIdx.x;
    const int b   = blockIdx.x;
    const int gtid = b * NT + tid;
    const int gstride = NB * NT;
    const int w   = tid >> 5;      // warp in block (0..7)
    const int l   = tid & 31;      // lane
    const int l2  = 2 * l;         // first of this lane's feature pair
    const int sub = tid >> 6;      // for pooling/head (4 groups of 64)
    const int f   = tid & 63;

    // ---- P0: init + dtype detect ----
    for (int i = gtid; i < NH / 4; i += gstride)
        ((float4*)g_x)[i] = ((const float4*)x)[i];
    for (int i = gtid; i < NN; i += gstride) g_deg[i] = 0;
    for (int i = gtid; i < LL*CC*128; i += gstride) g_stats[i] = 0.f;
    for (int i = gtid; i < GG*HH*LL; i += gstride) g_z[i] = 0.f;
    if (gtid < CC) g_ccnt[gtid] = 0;
    if (b == 0) {
        const int* e32 = (const int*)eidx;
        int bad = 0;
        for (int k = tid; k < 1024; k += NT) if (e32[2 * k + 1] != 0) bad = 1;
        int* sh = (int*)esh;
        sh[tid] = bad;
        __syncthreads();
        for (int s = 128; s > 0; s >>= 1) {
            if (tid < s) sh[tid] |= sh[tid + s];
            __syncthreads();
        }
        if (tid == 0) g_is64 = !sh[0];
    }
    grid_barrier();
    const int is64 = g_is64;

    // ---- P1: degree + cluster count ----
    for (int i = gtid; i < EE; i += gstride) {
        int d = load_idx(eidx, (long long)EE + i, is64);
        atomicAdd(&g_deg[d], 1);
    }
    for (int i = gtid; i < NN; i += gstride) atomicAdd(&g_ccnt[cl[i]], 1);
    grid_barrier();

    // ---- P2: cluster offsets (block0) + local inclusive degree scans ----
    if (b == 0 && tid == 0) {
        int acc = 0;
        for (int c = 0; c < CC; ++c) { g_coff[c] = acc; g_ccur[c] = acc; acc += g_ccnt[c]; }
        g_coff[CC] = acc;
    }
    {
        int* sh = (int*)esh;
        int idx = b * NODE_CHUNK + tid;
        int v = (tid < NODE_CHUNK && idx < NN) ? g_deg[idx] : 0;
        sh[tid] = v;
        __syncthreads();
        for (int s = 1; s < NT; s <<= 1) {
            int tv = (tid >= s) ? sh[tid - s] : 0;
            __syncthreads();
            sh[tid] += tv;
            __syncthreads();
        }
        if (tid < NODE_CHUNK && idx < NN) g_rowptr[idx] = sh[tid];
        if (tid == NT - 1) g_bsum[b] = sh[NT - 1];
    }
    grid_barrier();

    // ---- P3: scan block sums (block0); fill cluster lists (all) ----
    if (b == 0 && tid == 0) {
        int acc = 0;
        for (int i = 0; i < NB; ++i) { int t = g_bsum[i]; g_boff[i] = acc; acc += t; }
        g_rowptr[NN] = acc;
    }
    for (int i = gtid; i < NN; i += gstride) {
        int pos = atomicAdd(&g_ccur[cl[i]], 1);
        g_clist[pos] = i;
    }
    grid_barrier();

    // ---- P4: finalize rowptr/cursor ----
    {
        int idx = b * NODE_CHUNK + tid;
        if (tid < NODE_CHUNK && idx < NN) {
            int excl = g_boff[b] + g_rowptr[idx] - g_deg[idx];
            g_rowptr[idx] = excl;
            g_cursor[idx] = excl;
        }
    }
    grid_barrier();

    // ---- P5: CSR fill ----
    for (int i = gtid; i < EE; i += gstride) {
        int s = load_idx(eidx, i, is64);
        int d = load_idx(eidx, (long long)EE + i, is64);
        int pos = atomicAdd(&g_cursor[d], 1);
        g_csrc[pos] = s;
    }
    grid_barrier();

    // ---- main loop: 3 layers x 4 clusters; warp-per-node, f32x2 lanes ----
    const ull* Wsh1u = (const ull*)Wsh1;   // Wsh1[i*64 + 2l] pairs at index i*32+l
    const ull* Wsh2u = (const ull*)Wsh2;
    ull* hdup_u = (ull*)hdup[w];           // {h[i],h[i]} at index i

    for (int t = 0; t < LL; ++t) {
        for (int c = 0; c < CC; ++c) {
            const int tc = t * CC + c;
            for (int i = tid; i < 4096; i += NT) {
                Wsh1[i] = W1[tc * 4096 + i];
                Wsh2[i] = W2[tc * 4096 + i];
            }
            if (tid < 64) { s1sh[tid] = 0.f; s2sh[tid] = 0.f; }
            __syncthreads();

            const int lo  = g_coff[c];
            const int cnt = g_coff[c + 1] - lo;
            const int per = NB * 8;
            const int base = b * 8 + w;

            // === phase A: gather + mm1 + stats ===
            ull biasp = pack2(b1[tc * 64 + l2], b1[tc * 64 + l2 + 1]);
            ull a1p = 0ull, a2p = 0ull;
            int buf = 0;
            int node = 0, e0 = 0, deg = 0;
            ull xv = 0ull;
            if (base < cnt) {
                node = g_clist[lo + base];
                e0   = g_rowptr[node];
                deg  = g_rowptr[node + 1] - e0;
                xv   = ldgx2(node, l2);
                if (deg <= 64) {
                    if (l < deg)      esh[w][0][l]      = g_csrc[e0 + l];
                    if (l + 32 < deg) esh[w][0][l + 32] = g_csrc[e0 + l + 32];
                }
            }
            __syncwarp();

            for (int pos = base; pos < cnt; pos += per) {
                ull acc0 = xv, acc1 = 0ull, acc2 = 0ull, acc3 = 0ull;
                ull acc4 = 0ull, acc5 = 0ull, acc6 = 0ull, acc7 = 0ull;
                if (deg <= 64) {
                    const int* ep = esh[w][buf];
                    int i = 0;
                    for (; i + 8 <= deg; i += 8) {
                        int s0 = ep[i+0], s1 = ep[i+1], s2 = ep[i+2], s3 = ep[i+3];
                        int s4 = ep[i+4], s5 = ep[i+5], s6 = ep[i+6], s7 = ep[i+7];
                        acc0 = add2(acc0, ldgx2(s0, l2));
                        acc1 = add2(acc1, ldgx2(s1, l2));
                        acc2 = add2(acc2, ldgx2(s2, l2));
                        acc3 = add2(acc3, ldgx2(s3, l2));
                        acc4 = add2(acc4, ldgx2(s4, l2));
                        acc5 = add2(acc5, ldgx2(s5, l2));
                        acc6 = add2(acc6, ldgx2(s6, l2));
                        acc7 = add2(acc7, ldgx2(s7, l2));
                    }
                    for (; i < deg; ++i) acc0 = add2(acc0, ldgx2(ep[i], l2));
                } else {
                    // rare (deg>64): direct-global (broadcast csrc reads)
                    int e = e0;
                    const int e1 = e0 + deg;
                    for (; e + 8 <= e1; e += 8) {
                        int s0 = g_csrc[e+0], s1 = g_csrc[e+1], s2 = g_csrc[e+2], s3 = g_csrc[e+3];
                        int s4 = g_csrc[e+4], s5 = g_csrc[e+5], s6 = g_csrc[e+6], s7 = g_csrc[e+7];
                        acc0 = add2(acc0, ldgx2(s0, l2));
                        acc1 = add2(acc1, ldgx2(s1, l2));
                        acc2 = add2(acc2, ldgx2(s2, l2));
                        acc3 = add2(acc3, ldgx2(s3, l2));
                        acc4 = add2(acc4, ldgx2(s4, l2));
                        acc5 = add2(acc5, ldgx2(s5, l2));
                        acc6 = add2(acc6, ldgx2(s6, l2));
                        acc7 = add2(acc7, ldgx2(s7, l2));
                    }
                    for (; e < e1; ++e) acc0 = add2(acc0, ldgx2(g_csrc[e], l2));
                }
                ull hp = add2(add2(add2(acc0, acc1), add2(acc2, acc3)),
                              add2(add2(acc4, acc5), add2(acc6, acc7)));

                // prestage next node (own-lane writes; ordered by the syncwarps)
                int npos = pos + per;
                int nnode = 0, ne0 = 0, ndeg = 0;
                ull nxv = 0ull;
                if (npos < cnt) {
                    nnode = g_clist[lo + npos];
                    ne0   = g_rowptr[nnode];
                    ndeg  = g_rowptr[nnode + 1] - ne0;
                    nxv   = ldgx2(nnode, l2);
                    if (ndeg <= 64) {
                        if (l < ndeg)      esh[w][buf ^ 1][l]      = g_csrc[ne0 + l];
                        if (l + 32 < ndeg) esh[w][buf ^ 1][l + 32] = g_csrc[ne0 + l + 32];
                    }
                }
                // lane-duplicated h store: hdup[w][4l..4l+3] = {h0,h0,h1,h1}
                {
                    float h0, h1; unpack2(hp, h0, h1);
                    float4 v; v.x = h0; v.y = h0; v.z = h1; v.w = h1;
                    *(float4*)(&hdup[w][4 * l]) = v;
                }
                __syncwarp();
                // mm1: o[2l..2l+1] = bias + sum_i h[i] * W1[i][2l..2l+1]
                ull o0 = biasp, o1 = 0ull, o2 = 0ull, o3 = 0ull;
#pragma unroll
                for (int i = 0; i < 64; i += 4) {
                    fma2(o0, hdup_u[i+0], Wsh1u[(i+0) * 32 + l]);
                    fma2(o1, hdup_u[i+1], Wsh1u[(i+1) * 32 + l]);
                    fma2(o2, hdup_u[i+2], Wsh1u[(i+2) * 32 + l]);
                    fma2(o3, hdup_u[i+3], Wsh1u[(i+3) * 32 + l]);
                }
                ull o = add2(add2(o0, o1), add2(o2, o3));
                *(ull*)(g_h + (size_t)node * 64 + l2) = o;
                a1p = add2(a1p, o);
                fma2(a2p, o, o);
                __syncwarp();

                node = nnode; e0 = ne0; deg = ndeg; xv = nxv; buf ^= 1;
            }
            {
                float v0, v1;
                unpack2(a1p, v0, v1);
                atomicAdd(&s1sh[l2], v0); atomicAdd(&s1sh[l2 + 1], v1);
                unpack2(a2p, v0, v1);
                atomicAdd(&s2sh[l2], v0); atomicAdd(&s2sh[l2 + 1], v1);
            }
            __syncthreads();
            if (tid < 64) {
                atomicAdd(&g_stats[tc * 128 + tid],      s1sh[tid]);
                atomicAdd(&g_stats[tc * 128 + 64 + tid], s2sh[tid]);
            }
            grid_barrier();

            // === phase B: BN + ReLU + mm2, write back x ===
            float cnt_f = (float)max(cnt, 1);
            float mean0 = g_stats[tc * 128 + l2]     / cnt_f;
            float mean1 = g_stats[tc * 128 + l2 + 1] / cnt_f;
            float var0  = g_stats[tc * 128 + 64 + l2]     / cnt_f - mean0 * mean0;
            float var1  = g_stats[tc * 128 + 64 + l2 + 1] / cnt_f - mean1 * mean1;
            float inv0  = rsqrtf(var0 + 1e-5f) * g1[tc * 64 + l2];
            float inv1  = rsqrtf(var1 + 1e-5f) * g1[tc * 64 + l2 + 1];
            float beta0 = be1[tc * 64 + l2];
            float beta1 = be1[tc * 64 + l2 + 1];
            ull bias2p = pack2(b2[tc * 64 + l2], b2[tc * 64 + l2 + 1]);

            int node2 = 0;
            ull hv = 0ull;
            if (base < cnt) {
                node2 = g_clist[lo + base];
                hv    = *(const ull*)(g_h + (size_t)node2 * 64 + l2);
            }
            for (int pos = base; pos < cnt; pos += per) {
                float v0, v1; unpack2(hv, v0, v1);
                v0 = fmaxf((v0 - mean0) * inv0 + beta0, 0.f);
                v1 = fmaxf((v1 - mean1) * inv1 + beta1, 0.f);
                {
                    float4 v; v.x = v0; v.y = v0; v.z = v1; v.w = v1;
                    *(float4*)(&hdup[w][4 * l]) = v;
                }
                int npos = pos + per;
                int nnode = 0;
                ull nhv = 0ull;
                if (npos < cnt) {
                    nnode = g_clist[lo + npos];
                    nhv   = *(const ull*)(g_h + (size_t)nnode * 64 + l2);
                }
                __syncwarp();
                ull o0 = bias2p, o1 = 0ull, o2 = 0ull, o3 = 0ull;
#pragma unroll
                for (int i = 0; i < 64; i += 4) {
                    fma2(o0, hdup_u[i+0], Wsh2u[(i+0) * 32 + l]);
                    fma2(o1, hdup_u[i+1], Wsh2u[(i+1) * 32 + l]);
                    fma2(o2, hdup_u[i+2], Wsh2u[(i+2) * 32 + l]);
                    fma2(o3, hdup_u[i+3], Wsh2u[(i+3) * 32 + l]);
                }
                ull o = add2(add2(o0, o1), add2(o2, o3));
                *(ull*)(g_x + (size_t)node2 * 64 + l2) = o;
                __syncwarp();
                node2 = nnode; hv = nhv;
            }
            grid_barrier();
        }

        // ---- pooling for layer t: 256 blocks = 64 graphs x 4 chunks ----
        if (b < GG * 4) {
            float (*psh)[64] = (float(*)[64])hdup;
            int* lohi = (int*)esh;
            const int g  = b >> 2;
            const int ch = b & 3;
            if (tid < 2) {
                int target = g + tid;
                int lo2 = 0, hi2 = NN;
                while (lo2 < hi2) {
                    int m = (lo2 + hi2) >> 1;
                    if (load_idx(batch, m, is64) < target) lo2 = m + 1; else hi2 = m;
                }
                lohi[tid] = lo2;
            }
            __syncthreads();
            int lo2 = lohi[0], hi2 = lohi[1];
            int len = hi2 - lo2;
            int clo = lo2 + ((len * ch) >> 2);
            int chi = lo2 + ((len * (ch + 1)) >> 2);
            float s0 = 0.f, s1 = 0.f;
            int r = clo + sub;
            for (; r + 8 <= chi; r += 8) {
                s0 += g_x[r * 64 + f];
                s1 += g_x[(r + 4) * 64 + f];
            }
            for (; r < chi; r += 4) s0 += g_x[r * 64 + f];
            psh[sub][f] = s0 + s1;
            __syncthreads();
            if (sub == 0) {
                float v = psh[0][f] + psh[1][f] + psh[2][f] + psh[3][f];
                atomicAdd(&g_z[g * (HH * LL) + t * 64 + f], v);
            }
        }
        grid_barrier();
    }

    // ---- F1: h1[g] = z[g] @ Wp1 + bp1 ----
    if (b < GG) {
        float (*psh)[64] = (float(*)[64])hdup;
        float* zsh = Wsh1;
        if (tid < HH * LL) zsh[tid] = g_z[b * (HH * LL) + tid];
        __syncthreads();
        float p = 0.f;
        int k0 = sub * 48;
#pragma unroll
        for (int k = 0; k < 48; ++k) p += zsh[k0 + k] * Wp1[(k0 + k) * 64 + f];
        psh[sub][f] = p;
        __syncthreads();
        if (sub == 0)
            g_h1[b * 64 + f] = bp1[f] + ((psh[0][f] + psh[1][f]) + (psh[2][f] + psh[3][f]));
    }
    grid_barrier();

    // ---- F2: BN stats over graph rows (block 0) ----
    if (b == 0 && tid < 64) {
        float s = 0.f, q = 0.f;
        for (int g = 0; g < GG; ++g) { float v = g_h1[g * 64 + tid]; s += v; q += v * v; }
        float mean = s / (float)GG;
        float var  = q / (float)GG - mean * mean;
        g_bnp[tid]      = mean;
        g_bnp[64 + tid] = rsqrtf(var + 1e-5f) * gp[tid];
    }
    grid_barrier();

    // ---- F3: out[g] = relu(bn(h1[g])) @ Wp2 + bp2 ----
    if (b < GG) {
        float (*psh)[64] = (float(*)[64])hdup;
        float* vsh = Wsh1;
        if (tid < 64) {
            float v = g_h1[b * 64 + tid];
            vsh[tid] = fmaxf((v - g_bnp[tid]) * g_bnp[64 + tid] + bep[tid], 0.f);
        }
        __syncthreads();
        float p = 0.f;
        int k0 = sub * 16;
#pragma unroll
        for (int k = 0; k < 16; ++k) p += vsh[k0 + k] * Wp2[(k0 + k) * 64 + f];
        psh[sub][f] = p;
        __syncthreads();
        if (sub == 0)
            out[b * 64 + f] = bp2[f] + ((psh[0][f] + psh[1][f]) + (psh[2][f] + psh[3][f]));
    }
}

// ---------------------------------------------------------------------------
extern "C" void kernel_launch(void* const* d_in, const int* in_sizes, int n_in,
                              void* d_out, int out_size) {
    const float* x     = (const float*)d_in[0];
    const int*   cl    = (const int*)d_in[1];
    const void*  eidx  = d_in[2];
    const void*  batch = d_in[3];
    const float* W1  = (const float*)d_in[4];
    const float* b1  = (const float*)d_in[5];
    const float* g1  = (const float*)d_in[6];
    const float* be1 = (const float*)d_in[7];
    const float* W2  = (const float*)d_in[8];
    const float* b2  = (const float*)d_in[9];
    const float* Wp1 = (const float*)d_in[10];
    const float* bp1 = (const float*)d_in[11];
    const float* gp  = (const float*)d_in[12];
    const float* bep = (const float*)d_in[13];
    const float* Wp2 = (const float*)d_in[14];
    const float* bp2 = (const float*)d_in[15];
    float* out = (float*)d_out;

    persistent_kernel<<<NB, NT>>>(x, cl, eidx, batch, W1, b1, g1, be1, W2, b2,
                                  Wp1, bp1, gp, bep, Wp2, bp2, out);
}